// round 16
// baseline (speedup 1.0000x reference)
#include <cuda_runtime.h>
#include <mma.h>
#include <cstdint>

// InteractionArch via tf32 wmma split-GEMM + cp.async staging:
// out[b] = concat(dense[b](128),
//                 triu(k=1) of Gram([dense[b]; sparse[b].reshape(26,128)]))
// B=16384, D=128, F=26, OUTW=479.
//
// One warp = one sample. Staging: 27 cp.async.cg (16B/lane) move the raw
// fp32 rows gmem->smem with no register round-trip and full MLP -- this
// removes the LDG->convert->STS serial chain that latency-bound every wmma
// round (R10/R12/R14 all ~64us with issue ~32%).
// Split happens IN FRAGMENTS: load raw tf32 fragment, hi = x & 0xFFFFE000
// (top 19 bits = exact tf32), lo = trunc_tf32(x - hi).
// G = hi.hi^T + hi.lo^T + lo.hi^T (R10-validated 3-product form), 3 output
// tiles x 16 k-steps (k=8). G lands in the dead X smem region; the
// R12-proven per-row scatter emits the triu.

#define FF   26
#define OUTW 479

#define LDM   132                      // fp32 elems/row: 128 + 4 pad (528 B)
#define XW_F  (32 * LDM)               // floats per warp region
#define XW_B  (XW_F * 4)               // 16896 B per warp
#define G_LDM 36
#define SM_TOTAL (4 * XW_B)            // 67584 B per CTA

using namespace nvcuda;

__device__ __forceinline__ uint32_t smem_u32(const void* p)
{
    uint32_t a;
    asm("{ .reg .u64 t; cvta.to.shared.u64 t, %1; cvt.u32.u64 %0, t; }"
        : "=r"(a) : "l"(p));
    return a;
}

__device__ __forceinline__ float tf32_trunc(float x)
{
    return __uint_as_float(__float_as_uint(x) & 0xFFFFE000u);
}

__global__ void __launch_bounds__(128, 3)
interact_tf32(const float* __restrict__ dense,
              const float* __restrict__ sparse,
              float* __restrict__ out)
{
    extern __shared__ float smemf[];

    const int tid  = threadIdx.x;
    const int wid  = tid >> 5;
    const int lane = tid & 31;
    const int s    = blockIdx.x * 4 + wid;           // sample id

    float* X  = smemf + wid * XW_F;
    float* Gs = X;                                   // G reuses X when dead

    float* ob = out + (size_t)s * OUTW;
    const float* drow = dense  + (size_t)s * 128;
    const float* srow = sparse + (size_t)s * (FF * 128);

    const uint32_t xb = smem_u32(X);

    // ---- Stage: 27 rows via cp.async (16B per lane per row) ----
#pragma unroll
    for (int r = 0; r < 27; ++r) {
        const float* src = (r == 0) ? drow : srow + (r - 1) * 128;
        asm volatile("cp.async.cg.shared.global [%0], [%1], 16;"
                     :: "r"(xb + (r * LDM + 4 * lane) * 4),
                        "l"(src + 4 * lane) : "memory");
    }
    asm volatile("cp.async.commit_group;" ::: "memory");

    // Zero rows 27..31 while the copies fly (165 float4).
    {
        float4* zp = reinterpret_cast<float4*>(X + 27 * LDM);
#pragma unroll
        for (int j = 0; j < 6; ++j) {
            const int idx = j * 32 + lane;
            if (idx < 165)
                zp[idx] = make_float4(0.f, 0.f, 0.f, 0.f);
        }
    }

    asm volatile("cp.async.wait_group 0;" ::: "memory");
    __syncwarp();

    // ---- Dense passthrough (now smem-hot), coalesced ----
#pragma unroll
    for (int c = 0; c < 4; ++c)
        ob[c * 32 + lane] = X[c * 32 + lane];

    // ---- Gram: G = hi.hi^T + hi.lo^T + lo.hi^T, 16 k-steps of 8 ----
    wmma::fragment<wmma::accumulator, 16, 16, 8, float> c00, c01, c11;
    wmma::fill_fragment(c00, 0.0f);
    wmma::fill_fragment(c01, 0.0f);
    wmma::fill_fragment(c11, 0.0f);

#pragma unroll
    for (int k = 0; k < 16; ++k) {
        const float* pk = X + k * 8;

        wmma::fragment<wmma::matrix_a, 16, 16, 8, wmma::precision::tf32, wmma::row_major> a0, a1, ah, al;
        wmma::fragment<wmma::matrix_b, 16, 16, 8, wmma::precision::tf32, wmma::col_major> b0, b1, bh, bl;

        wmma::load_matrix_sync(a0, pk,            LDM);   // rows 0-15
        wmma::load_matrix_sync(a1, pk + 16 * LDM, LDM);   // rows 16-31
        wmma::load_matrix_sync(b0, pk,            LDM);   // cols(n) 0-15
        wmma::load_matrix_sync(b1, pk + 16 * LDM, LDM);   // cols(n) 16-31

        // ---- tile (0,0): a0 x b0 ----
#pragma unroll
        for (int i = 0; i < a0.num_elements; ++i) {
            ah.x[i] = tf32_trunc(a0.x[i]);
            al.x[i] = tf32_trunc(a0.x[i] - ah.x[i]);
        }
#pragma unroll
        for (int i = 0; i < b0.num_elements; ++i) {
            bh.x[i] = tf32_trunc(b0.x[i]);
            bl.x[i] = tf32_trunc(b0.x[i] - bh.x[i]);
        }
        wmma::mma_sync(c00, ah, bh, c00);
        wmma::mma_sync(c00, ah, bl, c00);
        wmma::mma_sync(c00, al, bh, c00);

        // ---- tile (0,1): a0 x b1 (ah/al still valid) ----
#pragma unroll
        for (int i = 0; i < b1.num_elements; ++i) {
            bh.x[i] = tf32_trunc(b1.x[i]);
            bl.x[i] = tf32_trunc(b1.x[i] - bh.x[i]);
        }
        wmma::mma_sync(c01, ah, bh, c01);
        wmma::mma_sync(c01, ah, bl, c01);
        wmma::mma_sync(c01, al, bh, c01);

        // ---- tile (1,1): a1 x b1 (bh/bl still valid) ----
#pragma unroll
        for (int i = 0; i < a1.num_elements; ++i) {
            ah.x[i] = tf32_trunc(a1.x[i]);
            al.x[i] = tf32_trunc(a1.x[i] - ah.x[i]);
        }
        wmma::mma_sync(c11, ah, bh, c11);
        wmma::mma_sync(c11, ah, bl, c11);
        wmma::mma_sync(c11, al, bh, c11);
    }

    // ---- X dead: reuse as 32x36 f32 G scratch ----
    __syncwarp();
    wmma::store_matrix_sync(Gs,                   c00, G_LDM, wmma::mem_row_major);
    wmma::store_matrix_sync(Gs + 16,              c01, G_LDM, wmma::mem_row_major);
    wmma::store_matrix_sync(Gs + 16 * G_LDM + 16, c11, G_LDM, wmma::mem_row_major);
    __syncwarp();

    // ---- Scatter triu (R12-proven): lane f emits (f, g), g = f+1..26 ----
    const int f = lane;
    if (f < 26) {
        const int rb = 128 + f * 26 - (f * (f - 1)) / 2 - f - 1;
        for (int g = f + 1; g < 27; ++g)
            ob[rb + g] = Gs[f * G_LDM + g];
    }
}

extern "C" void kernel_launch(void* const* d_in, const int* in_sizes, int n_in,
                              void* d_out, int out_size)
{
    const float* dense  = (const float*)d_in[0];
    const float* sparse = (const float*)d_in[1];
    float* out = (float*)d_out;

    cudaFuncSetAttribute(interact_tf32,
                         cudaFuncAttributeMaxDynamicSharedMemorySize, SM_TOTAL);

    // 16384 samples / 4 per CTA -> 4096 CTAs of 128 threads; 3 CTAs/SM.
    interact_tf32<<<4096, 128, SM_TOTAL>>>(dense, sparse, out);
}

// round 17
// speedup vs baseline: 1.4513x; 1.4513x over previous
#include <cuda_runtime.h>
#include <cuda_bf16.h>
#include <mma.h>
#include <cstdint>

// InteractionArch via bf16 wmma split-GEMM (R12 math, byte-identical) with
// cp.async staging to unlock HBM bandwidth:
// out[b] = concat(dense[b](128),
//                 triu(k=1) of Gram([dense[b]; sparse[b].reshape(26,128)]))
// B=16384, D=128, F=26, OUTW=479.
//
// Diagnosis R4/R10/R12: all plateau at HBM ~3.9TB/s = Little's-law limit of
// register-batched LDGs (~5 in flight/warp, 577cyc stalls). Fix: stage each
// 64-dim half with 27 cp.async (8B/lane) -- all in flight at once, no reg
// round-trip -- into the SAME smem bytes the bf16 hi|lo tile occupies
// (fp32 half-row = 256B = hi|lo row), then convert IN PLACE (batches of 4
// rows, __syncwarp between batch-read and batch-write kills the WAR hazard).
// Compute/epilogue identical to R12: hi=rn_bf16(x), lo=rn_bf16(x-hi),
// G = hi.hi^T + hi.lo^T + lo.hi^T; 3 tiles x 8 ksteps x 3 mma; rel 4.45e-6.

#define FF   26
#define OUTW 479

#define LDM   136                    // 64 hi + 64 lo + 8 pad bf16 (272 B/row)
#define XW_B  (32 * LDM * 2)         // 8704 B per-warp tile
#define G_LDM 36                     // f32 elems/row of G scratch (reuses X)
#define SM_TOTAL (4 * XW_B)          // 34816 B per CTA

using namespace nvcuda;

__device__ __forceinline__ uint32_t smem_u32(const void* p)
{
    uint32_t a;
    asm("{ .reg .u64 t; cvta.to.shared.u64 t, %1; cvt.u32.u64 %0, t; }"
        : "=r"(a) : "l"(p));
    return a;
}

__global__ void __launch_bounds__(128)
interact_wmma(const float* __restrict__ dense,
              const float* __restrict__ sparse,
              float* __restrict__ out)
{
    extern __shared__ char smem[];

    const int tid  = threadIdx.x;
    const int wid  = tid >> 5;
    const int lane = tid & 31;
    const int s    = blockIdx.x * 4 + wid;      // sample id

    char*          Xc = smem + wid * XW_B;
    __nv_bfloat16* X  = reinterpret_cast<__nv_bfloat16*>(Xc);
    float*         Gs = reinterpret_cast<float*>(Xc);

    float* ob = out + (size_t)s * OUTW;
    const float* drow = dense  + (size_t)s * 128;
    const float* srow = sparse + (size_t)s * (FF * 128);

    const uint32_t xb = smem_u32(Xc);

    // Zero bf16 rows 27..31 once (5 rows x 272 B = 85 uint4).
    {
        uint4* zp = reinterpret_cast<uint4*>(Xc + 27 * 272);
#pragma unroll
        for (int j = 0; j < 3; ++j) {
            const int idx = j * 32 + lane;
            if (idx < 85)
                zp[idx] = make_uint4(0, 0, 0, 0);
        }
    }

    wmma::fragment<wmma::accumulator, 16, 16, 16, float> c00, c01, c11;
    wmma::fill_fragment(c00, 0.0f);
    wmma::fill_fragment(c01, 0.0f);
    wmma::fill_fragment(c11, 0.0f);

#pragma unroll
    for (int h = 0; h < 2; ++h) {
        // ---- Stage this half: 27 rows x 256B via cp.async (8B/lane) ----
#pragma unroll
        for (int r = 0; r < 27; ++r) {
            const float* src = ((r == 0) ? drow : srow + (r - 1) * 128)
                               + h * 64 + 2 * lane;
            asm volatile("cp.async.ca.shared.global [%0], [%1], 8;"
                         :: "r"(xb + r * 272 + 8 * lane), "l"(src) : "memory");
        }
        asm volatile("cp.async.commit_group;" ::: "memory");
        asm volatile("cp.async.wait_group 0;" ::: "memory");
        __syncwarp();

        // ---- Dense passthrough for this half (row 0 still raw fp32) ----
        {
            const float2 dv = reinterpret_cast<const float2*>(Xc)[lane];
            ob[h * 64 + 2 * lane]     = dv.x;
            ob[h * 64 + 2 * lane + 1] = dv.y;
        }

        // ---- Convert in place: fp32 half-row (256B) -> hi|lo bf16 ----
        // Batch 4 rows: read all lanes' float2 first, sync, then write.
#pragma unroll
        for (int b = 0; b < 7; ++b) {
            const int r0 = b * 4;
            const int nr = (b == 6) ? 3 : 4;
            float2 f[4];
#pragma unroll
            for (int j = 0; j < 4; ++j)
                if (j < nr)
                    f[j] = *reinterpret_cast<const float2*>(
                               Xc + (r0 + j) * 272 + 8 * lane);
            __syncwarp();
#pragma unroll
            for (int j = 0; j < 4; ++j) {
                if (j < nr) {
                    __nv_bfloat162 hp = __floats2bfloat162_rn(f[j].x, f[j].y);
                    const uint32_t hw = reinterpret_cast<uint32_t&>(hp);
                    const float l0 = f[j].x - __uint_as_float(hw << 16);
                    const float l1 = f[j].y - __uint_as_float(hw & 0xFFFF0000u);
                    __nv_bfloat162 lp = __floats2bfloat162_rn(l0, l1);
                    *reinterpret_cast<uint32_t*>(Xc + (r0 + j) * 272 + 4 * lane) = hw;
                    *reinterpret_cast<uint32_t*>(Xc + (r0 + j) * 272 + 128 + 4 * lane)
                        = reinterpret_cast<uint32_t&>(lp);
                }
            }
        }
        __syncwarp();

        // ---- 4 k-steps over this half's 64 dims (identical to R12) ----
#pragma unroll
        for (int k = 0; k < 4; ++k) {
            wmma::fragment<wmma::matrix_a, 16, 16, 16, __nv_bfloat16, wmma::row_major> a0h, a0l, a1h, a1l;
            wmma::fragment<wmma::matrix_b, 16, 16, 16, __nv_bfloat16, wmma::col_major> b0h, b0l, b1h, b1l;

            wmma::load_matrix_sync(a0h, X +                 k * 16, LDM);
            wmma::load_matrix_sync(a0l, X +            64 + k * 16, LDM);
            wmma::load_matrix_sync(a1h, X + 16 * LDM +      k * 16, LDM);
            wmma::load_matrix_sync(a1l, X + 16 * LDM + 64 + k * 16, LDM);
            wmma::load_matrix_sync(b0h, X +                 k * 16, LDM);
            wmma::load_matrix_sync(b0l, X +            64 + k * 16, LDM);
            wmma::load_matrix_sync(b1h, X + 16 * LDM +      k * 16, LDM);
            wmma::load_matrix_sync(b1l, X + 16 * LDM + 64 + k * 16, LDM);

            wmma::mma_sync(c00, a0h, b0h, c00);
            wmma::mma_sync(c00, a0h, b0l, c00);
            wmma::mma_sync(c00, a0l, b0h, c00);

            wmma::mma_sync(c01, a0h, b1h, c01);
            wmma::mma_sync(c01, a0h, b1l, c01);
            wmma::mma_sync(c01, a0l, b1h, c01);

            wmma::mma_sync(c11, a1h, b1h, c11);
            wmma::mma_sync(c11, a1h, b1l, c11);
            wmma::mma_sync(c11, a1l, b1h, c11);
        }
        __syncwarp();   // half h reads done before half h+1 overwrites X
    }

    // ---- X dead: reuse region as 32x36 f32 G scratch ----
    wmma::store_matrix_sync(Gs,                   c00, G_LDM, wmma::mem_row_major);
    wmma::store_matrix_sync(Gs + 16,              c01, G_LDM, wmma::mem_row_major);
    wmma::store_matrix_sync(Gs + 16 * G_LDM + 16, c11, G_LDM, wmma::mem_row_major);
    __syncwarp();

    // ---- Scatter triu (R12-proven): lane f emits (f, g), g = f+1..26 ----
    const int f = lane;
    if (f < 26) {
        const int rb = 128 + f * 26 - (f * (f - 1)) / 2 - f - 1;
        for (int g = f + 1; g < 27; ++g)
            ob[rb + g] = Gs[f * G_LDM + g];
    }
}

extern "C" void kernel_launch(void* const* d_in, const int* in_sizes, int n_in,
                              void* d_out, int out_size)
{
    const float* dense  = (const float*)d_in[0];
    const float* sparse = (const float*)d_in[1];
    float* out = (float*)d_out;

    // 16384 samples / 4 per CTA -> 4096 CTAs of 128 threads; 34816 B smem
    // -> 6 CTAs/SM (24 warps), same occupancy as R12 but full-MLP staging.
    interact_wmma<<<4096, 128, SM_TOTAL>>>(dense, sparse, out);
}